// round 7
// baseline (speedup 1.0000x reference)
#include <cuda_runtime.h>
#include <cstdint>

#define N_NODES 100000
#define N_EDGES 1600000
#define D 128

// ---------------------------------------------------------------------------
// Scratch (device globals; no allocation allowed).
// ---------------------------------------------------------------------------
__device__ float g_Wt[D * D];                    // W transposed: g_Wt[k*D+o] = W[o][k]
__device__ int   g_deg[N_NODES];
__device__ int   g_row[N_NODES + 1];
__device__ int   g_cursor[N_NODES];
__device__ int   g_bsum[512];
__device__ int   g_csr[N_EDGES];                 // src node ids grouped by dst
__device__ int   g_idx64;

// ---------------------------------------------------------------------------
// Detect whether index arrays are int64 or int32 (see round 0 rationale).
// ---------------------------------------------------------------------------
__global__ void detect_idx_kernel(const void* __restrict__ src_raw) {
    const long long* p = (const long long*)src_raw;
    int ok = 1;
    for (int i = 0; i < 128; i++) {
        long long v = p[i];
        if (v < 0 || v >= N_NODES) { ok = 0; break; }
    }
    g_idx64 = ok;
}

// ---------------------------------------------------------------------------
// One-time W transpose into global.
// ---------------------------------------------------------------------------
__global__ void prep_w_kernel(const float* __restrict__ W) {
    int k = blockIdx.x;
    for (int o = threadIdx.x; o < D; o += blockDim.x)
        g_Wt[k * D + o] = W[o * D + k];
}

// ---------------------------------------------------------------------------
// Vectorized index fetch: 4 consecutive edges starting at 4*t.
// ---------------------------------------------------------------------------
__device__ __forceinline__ void load_idx4(const void* raw, int t, int idx[4]) {
    if (g_idx64) {
        longlong2 a = ((const longlong2*)raw)[2 * t];
        longlong2 b = ((const longlong2*)raw)[2 * t + 1];
        idx[0] = (int)a.x; idx[1] = (int)a.y;
        idx[2] = (int)b.x; idx[3] = (int)b.y;
    } else {
        int4 v = ((const int4*)raw)[t];
        idx[0] = v.x; idx[1] = v.y; idx[2] = v.z; idx[3] = v.w;
    }
}

// ---------------------------------------------------------------------------
// CSR build: histogram (4 edges/thread) -> scan (3 kernels) -> fill (4/thread).
// g_deg is zeroed by cudaMemsetAsync before hist.
// ---------------------------------------------------------------------------
__global__ __launch_bounds__(256) void hist_kernel(const void* __restrict__ dst_raw) {
    int t = blockIdx.x * blockDim.x + threadIdx.x;
    if (t >= N_EDGES / 4) return;
    int d[4];
    load_idx4(dst_raw, t, d);
    atomicAdd(&g_deg[d[0]], 1);
    atomicAdd(&g_deg[d[1]], 1);
    atomicAdd(&g_deg[d[2]], 1);
    atomicAdd(&g_deg[d[3]], 1);
}

#define SCAN_B 512
__global__ void scan1_kernel() {       // grid 196, block 512
    __shared__ int s[SCAN_B];
    int gid = blockIdx.x * SCAN_B + threadIdx.x;
    int v = (gid < N_NODES) ? g_deg[gid] : 0;
    s[threadIdx.x] = v;
    __syncthreads();
    for (int off = 1; off < SCAN_B; off <<= 1) {
        int t = (threadIdx.x >= off) ? s[threadIdx.x - off] : 0;
        __syncthreads();
        s[threadIdx.x] += t;
        __syncthreads();
    }
    if (gid < N_NODES) g_row[gid] = s[threadIdx.x] - v;   // exclusive within block
    if (threadIdx.x == SCAN_B - 1) g_bsum[blockIdx.x] = s[SCAN_B - 1];
}

__global__ void scan2_kernel(int nblocks) {   // 1 block, 512 threads
    __shared__ int s[SCAN_B];
    int v = (threadIdx.x < nblocks) ? g_bsum[threadIdx.x] : 0;
    s[threadIdx.x] = v;
    __syncthreads();
    for (int off = 1; off < SCAN_B; off <<= 1) {
        int t = (threadIdx.x >= off) ? s[threadIdx.x - off] : 0;
        __syncthreads();
        s[threadIdx.x] += t;
        __syncthreads();
    }
    g_bsum[threadIdx.x] = s[threadIdx.x] - v;             // exclusive block offsets
}

__global__ void scan3_kernel() {
    int gid = blockIdx.x * blockDim.x + threadIdx.x;
    if (gid < N_NODES) {
        int r = g_row[gid] + g_bsum[gid >> 9];
        g_row[gid] = r;
        g_cursor[gid] = r;
    }
    if (gid == 0) g_row[N_NODES] = N_EDGES;
}

__global__ __launch_bounds__(256) void fill_kernel(const void* __restrict__ src_raw,
                                                   const void* __restrict__ dst_raw) {
    int t = blockIdx.x * blockDim.x + threadIdx.x;
    if (t >= N_EDGES / 4) return;
    int d[4], s[4];
    load_idx4(dst_raw, t, d);
    load_idx4(src_raw, t, s);
    #pragma unroll
    for (int i = 0; i < 4; i++) {
        int p = atomicAdd(&g_cursor[d[i]], 1);
        g_csr[p] = s[i];
    }
}

// ---------------------------------------------------------------------------
// FUSED gather + SGEMM + bias.
// 64x128 tile per CTA, 256 threads, 2 CTAs/SM (reg cap 128 via launch_bounds).
// Phase A: warp w gathers nodes rb+8w..rb+8w+7 straight into As (no g_agg).
// Phase B: conflict-free f32x2 register-blocked GEMM (round-4/5 design).
// Cross-CTA overlap: one CTA's FMA phase hides its co-resident CTA's
// L2-latency-bound gather phase.
// ---------------------------------------------------------------------------
#define AS_STRIDE 132
#define GEMM_THREADS 256
#define GEMM_BLOCKS ((N_NODES + 63) / 64)

__device__ __forceinline__ unsigned long long pack2(float a) {
    unsigned long long r;
    asm("mov.b64 %0, {%1, %1};" : "=l"(r) : "f"(a));
    return r;
}
__device__ __forceinline__ unsigned long long fma2(unsigned long long a,
                                                   unsigned long long b,
                                                   unsigned long long c) {
    unsigned long long d;
    asm("fma.rn.f32x2 %0, %1, %2, %3;" : "=l"(d) : "l"(a), "l"(b), "l"(c));
    return d;
}

__global__ __launch_bounds__(GEMM_THREADS, 2) void fused_kernel(
    const float* __restrict__ x,
    const float* __restrict__ b,
    float* __restrict__ out)
{
    extern __shared__ float smem[];
    float* As = smem;                       // [64][AS_STRIDE]
    float* Wt = smem + 64 * AS_STRIDE;      // [128][128] (k-major)
    float* bs = Wt + D * D;                 // [128]

    const int tid = threadIdx.x;
    const int rb  = blockIdx.x * 64;
    const int w   = tid >> 5;
    const int ln  = tid & 31;

    // W tile: pre-transposed in global -> straight coalesced copy.
    for (int i = tid; i < 128 * 32; i += GEMM_THREADS) {
        int k = i >> 5, c4 = i & 31;
        *(float4*)(Wt + k * D + c4 * 4) = *(const float4*)(g_Wt + k * D + c4 * 4);
    }
    if (tid < D) bs[tid] = b[tid];

    // Phase A: gather. Warp w owns tile rows [8w, 8w+8); lane owns one float4.
    const float4* __restrict__ xv = (const float4*)x;
    #pragma unroll 1
    for (int i = 0; i < 8; i++) {
        int r = w * 8 + i;
        int node = rb + r;
        float4 acc = make_float4(0.f, 0.f, 0.f, 0.f);
        if (node < N_NODES) {
            int beg = g_row[node];
            int end = g_row[node + 1];
            int j = beg;
            for (; j + 8 <= end; j += 8) {
                int s[8];
                #pragma unroll
                for (int u = 0; u < 8; u++) s[u] = g_csr[j + u];
                float4 v[8];
                #pragma unroll
                for (int u = 0; u < 8; u++) v[u] = xv[(size_t)s[u] * 32 + ln];
                #pragma unroll
                for (int u = 0; u < 8; u++) {
                    acc.x += v[u].x; acc.y += v[u].y;
                    acc.z += v[u].z; acc.w += v[u].w;
                }
            }
            for (; j < end; j++) {
                float4 v = xv[(size_t)g_csr[j] * 32 + ln];
                acc.x += v.x; acc.y += v.y; acc.z += v.z; acc.w += v.w;
            }
        }
        *(float4*)(As + r * AS_STRIDE + ln * 4) = acc;
    }
    __syncthreads();

    // Phase B: GEMM. Thread (tx,ty): rows 4ty..+3, cols {2tx+32g,+1} g=0..3.
    const int tx = tid & 15, ty = tid >> 4;
    const int r0 = ty * 4;

    unsigned long long acc[4][4];
    {
        const unsigned long long* bp = (const unsigned long long*)bs;
        #pragma unroll
        for (int g = 0; g < 4; g++) {
            unsigned long long bv = bp[tx + 16 * g];
            #pragma unroll
            for (int i = 0; i < 4; i++) acc[i][g] = bv;
        }
    }

    #pragma unroll 8
    for (int k = 0; k < 128; k++) {
        const unsigned long long* wp = (const unsigned long long*)(Wt + k * D);
        unsigned long long w0 = wp[tx];
        unsigned long long w1 = wp[tx + 16];
        unsigned long long w2 = wp[tx + 32];
        unsigned long long w3 = wp[tx + 48];

        unsigned long long a2[4];
        #pragma unroll
        for (int i = 0; i < 4; i++)
            a2[i] = pack2(As[(r0 + i) * AS_STRIDE + k]);

        #pragma unroll
        for (int i = 0; i < 4; i++) {
            acc[i][0] = fma2(a2[i], w0, acc[i][0]);
            acc[i][1] = fma2(a2[i], w1, acc[i][1]);
            acc[i][2] = fma2(a2[i], w2, acc[i][2]);
            acc[i][3] = fma2(a2[i], w3, acc[i][3]);
        }
    }

    #pragma unroll
    for (int i = 0; i < 4; i++) {
        int grow = rb + r0 + i;
        if (grow < N_NODES) {
            unsigned long long* dst =
                (unsigned long long*)(out + (size_t)grow * D + 2 * tx);
            dst[0]  = acc[i][0];
            dst[16] = acc[i][1];
            dst[32] = acc[i][2];
            dst[48] = acc[i][3];
        }
    }
}

// ---------------------------------------------------------------------------
// Launch
// ---------------------------------------------------------------------------
extern "C" void kernel_launch(void* const* d_in, const int* in_sizes, int n_in,
                              void* d_out, int out_size) {
    const float* x   = (const float*)d_in[0];
    const void*  src = d_in[1];
    const void*  dst = d_in[2];
    const float* W   = (const float*)d_in[3];
    const float* b   = (const float*)d_in[4];
    float* out = (float*)d_out;

    const int fused_smem = (64 * AS_STRIDE + D * D + D) * (int)sizeof(float);

    static int inited = 0;
    static void* deg_ptr = nullptr;
    if (!inited) {
        cudaFuncSetAttribute(fused_kernel,
                             cudaFuncAttributeMaxDynamicSharedMemorySize,
                             fused_smem);
        cudaGetSymbolAddress(&deg_ptr, g_deg);
        inited = 1;
    }

    const int scan_blocks = (N_NODES + SCAN_B - 1) / SCAN_B;  // 196

    detect_idx_kernel<<<1, 1>>>(src);
    prep_w_kernel<<<D, 128>>>(W);

    cudaMemsetAsync(deg_ptr, 0, N_NODES * sizeof(int));
    hist_kernel<<<(N_EDGES / 4 + 255) / 256, 256>>>(dst);
    scan1_kernel<<<scan_blocks, SCAN_B>>>();
    scan2_kernel<<<1, SCAN_B>>>(scan_blocks);
    scan3_kernel<<<(N_NODES + 255) / 256, 256>>>();
    fill_kernel<<<(N_EDGES / 4 + 255) / 256, 256>>>(src, dst);

    fused_kernel<<<GEMM_BLOCKS, GEMM_THREADS, fused_smem>>>(x, b, out);
}